// round 4
// baseline (speedup 1.0000x reference)
#include <cuda_runtime.h>
#include <math.h>

// Problem constants
#define Bn   65536
#define Dn   784
#define Hn   392
#define Ln   32
#define BM   64          // rows per CTA
#define NT   256         // threads per CTA
#define HSs  394         // hs row stride (padded, even for float2)
#define ZSs  33          // zs row stride
#define NCTA (Bn/BM)     // 1024

// smem layout (floats): hs[BM][HSs] | zs[BM][ZSs] | staging union (4160 floats)
#define SM_HS    0
#define SM_ZS    (BM*HSs)                 // 25216
#define SM_STG   (SM_ZS + BM*ZSs)         // 27328
#define SM_FLOATS (SM_STG + 4160)         // 31488
#define SMEM_BYTES (SM_FLOATS*4)          // 125952

typedef unsigned long long ull;

__device__ __forceinline__ ull dup2(float v) {
    ull r; asm("mov.b64 %0, {%1, %1};" : "=l"(r) : "f"(v)); return r;
}
__device__ __forceinline__ ull fma2(ull a, ull b, ull c) {
    ull d; asm("fma.rn.f32x2 %0, %1, %2, %3;" : "=l"(d) : "l"(a), "l"(b), "l"(c)); return d;
}
__device__ __forceinline__ float2 unp(ull v) {
    float2 r; asm("mov.b64 {%0, %1}, %2;" : "=f"(r.x), "=f"(r.y) : "l"(v)); return r;
}

// per-CTA partial sums: [cta][0] = sum(0.5*lv + (x-mu)^2/ex), [cta][1] = raw kl terms
__device__ float g_part[NCTA * 2];

__global__ __launch_bounds__(NT, 1)
void vae_fused(const float* __restrict__ x,     const float* __restrict__ eps_z,
               const float* __restrict__ eps_y,
               const float* __restrict__ W_e1,  const float* __restrict__ b_e1,
               const float* __restrict__ W_emu, const float* __restrict__ b_emu,
               const float* __restrict__ W_elv, const float* __restrict__ b_elv,
               const float* __restrict__ W_d1,  const float* __restrict__ b_d1,
               const float* __restrict__ W_dmu, const float* __restrict__ b_dmu,
               const float* __restrict__ W_dlv, const float* __restrict__ b_dlv,
               float* __restrict__ out)
{
    extern __shared__ float smem[];
    float* hs  = smem + SM_HS;    // h, later hd: [BM][HSs]
    float* zs  = smem + SM_ZS;    // z: [BM][ZSs]
    float* stg = smem + SM_STG;   // staging union

    const int tid   = threadIdx.x;
    const int row0  = blockIdx.x * BM;
    const int pc    = tid & 15;        // pair-column lane (0..15)
    const int rbase = (tid >> 4) * 4;  // 4 rows per thread

    float nll_acc = 0.f, kl_acc = 0.f;

    // ================= Phase A: h = relu(x @ W_e1^T + b_e1) -> hs =================
    {
        float* xs = stg;            // [64][16]
        float* ws = stg + BM * 16;  // [16][130] (pad for STS conflicts, even stride)
        for (int nc = 0; nc < 4; ++nc) {
            const int pbase = nc * 64;                 // pair base (196 pairs total)
            const int npch  = (nc < 3) ? 64 : 4;
            ull acc[4][4];
            #pragma unroll
            for (int r = 0; r < 4; ++r)
                #pragma unroll
                for (int j = 0; j < 4; ++j) acc[r][j] = 0ull;

            for (int kc = 0; kc < 49; ++kc) {          // K = 784 = 49*16
                const int kb = kc * 16;
                __syncthreads();
                {   // stage x chunk: one float4 per thread
                    int m = tid >> 2, q = tid & 3;
                    float4 v = *reinterpret_cast<const float4*>(
                        x + (size_t)(row0 + m) * Dn + kb + q * 4);
                    *reinterpret_cast<float4*>(xs + m * 16 + q * 4) = v;
                }
                #pragma unroll
                for (int i = 0; i < 8; ++i) {          // stage W_e1 chunk transposed
                    int idx = tid + NT * i;
                    int c = idx >> 4, k = idx & 15;
                    int gc = pbase * 2 + c;
                    ws[k * 130 + c] = (gc < Hn) ? W_e1[(size_t)gc * Dn + kb + k] : 0.f;
                }
                __syncthreads();
                #pragma unroll
                for (int kk = 0; kk < 16; ++kk) {
                    ull a0 = dup2(xs[(rbase + 0) * 16 + kk]);
                    ull a1 = dup2(xs[(rbase + 1) * 16 + kk]);
                    ull a2 = dup2(xs[(rbase + 2) * 16 + kk]);
                    ull a3 = dup2(xs[(rbase + 3) * 16 + kk]);
                    #pragma unroll
                    for (int j = 0; j < 4; ++j) {
                        ull w = *reinterpret_cast<const ull*>(ws + kk * 130 + 2 * (pc + 16 * j));
                        acc[0][j] = fma2(a0, w, acc[0][j]);
                        acc[1][j] = fma2(a1, w, acc[1][j]);
                        acc[2][j] = fma2(a2, w, acc[2][j]);
                        acc[3][j] = fma2(a3, w, acc[3][j]);
                    }
                }
            }
            #pragma unroll
            for (int j = 0; j < 4; ++j) {
                int p = pc + 16 * j;
                if (p < npch) {
                    int c0 = (pbase + p) * 2;
                    float bb0 = b_e1[c0], bb1 = b_e1[c0 + 1];
                    #pragma unroll
                    for (int r = 0; r < 4; ++r) {
                        float2 a = unp(acc[r][j]);
                        float2 v;
                        v.x = fmaxf(a.x + bb0, 0.f);
                        v.y = fmaxf(a.y + bb1, 0.f);
                        *reinterpret_cast<float2*>(hs + (rbase + r) * HSs + c0) = v;
                    }
                }
            }
        }
    }

    // ================= Phase B: mu_z / logvar_z / z / kl =================
    {
        float* wem = stg;             // [56][34]
        float* wel = stg + 56 * 34;   // [56][34]
        const int g = tid & 3;        // l-pair subgroup
        const int m = tid >> 2;       // row (0..63)
        ull amu[4], alv[4];
        #pragma unroll
        for (int i = 0; i < 4; ++i) { amu[i] = 0ull; alv[i] = 0ull; }

        for (int jc = 0; jc < 7; ++jc) {               // H = 392 = 7*56
            int jb = jc * 56;
            __syncthreads();
            #pragma unroll
            for (int i = 0; i < 7; ++i) {              // 1792 elems per matrix
                int idx = tid + NT * i;
                int l = idx / 56, jj = idx % 56;
                wem[jj * 34 + l] = W_emu[l * Hn + jb + jj];
                wel[jj * 34 + l] = W_elv[l * Hn + jb + jj];
            }
            __syncthreads();
            #pragma unroll 8
            for (int jj = 0; jj < 56; ++jj) {
                ull a = dup2(hs[m * HSs + jb + jj]);
                #pragma unroll
                for (int i = 0; i < 4; ++i) {
                    int p = g + 4 * i;
                    amu[i] = fma2(a, *reinterpret_cast<const ull*>(wem + jj * 34 + 2 * p), amu[i]);
                    alv[i] = fma2(a, *reinterpret_cast<const ull*>(wel + jj * 34 + 2 * p), alv[i]);
                }
            }
        }
        int grow = row0 + m;
        #pragma unroll
        for (int i = 0; i < 4; ++i) {
            int p = g + 4 * i, l0 = 2 * p;
            float2 am = unp(amu[i]), av = unp(alv[i]);
            float mu0 = fmaxf(am.x + b_emu[l0], 0.f);
            float mu1 = fmaxf(am.y + b_emu[l0 + 1], 0.f);
            float lv0 = fmaxf(av.x + b_elv[l0], 0.f);
            float lv1 = fmaxf(av.y + b_elv[l0 + 1], 0.f);
            float e0 = expf(lv0), e1 = expf(lv1);
            float z0 = mu0 + eps_z[grow * Ln + l0]     * expf(0.5f * lv0);
            float z1 = mu1 + eps_z[grow * Ln + l0 + 1] * expf(0.5f * lv1);
            zs[m * ZSs + l0]     = z0;
            zs[m * ZSs + l0 + 1] = z1;
            kl_acc += (mu0 * mu0 + e0 - logf(1e-8f + e0) - 1.f)
                    + (mu1 * mu1 + e1 - logf(1e-8f + e1) - 1.f);
        }
    }

    // ================= Phase C: hd = relu(z @ W_d1^T + b_d1) -> hs (overwrite) ====
    {
        float* wd = stg;  // [32][130]
        for (int nc = 0; nc < 4; ++nc) {
            const int pbase = nc * 64;
            const int npch  = (nc < 3) ? 64 : 4;
            __syncthreads();   // first iter also fences phase-B hs reads / zs writes
            #pragma unroll
            for (int i = 0; i < 16; ++i) {             // 4096 elems
                int idx = tid + NT * i;
                int c = idx >> 5, k = idx & 31;
                int gc = pbase * 2 + c;
                wd[k * 130 + c] = (gc < Hn) ? W_d1[gc * Ln + k] : 0.f;
            }
            __syncthreads();
            ull acc[4][4];
            #pragma unroll
            for (int r = 0; r < 4; ++r)
                #pragma unroll
                for (int j = 0; j < 4; ++j) acc[r][j] = 0ull;
            #pragma unroll 8
            for (int k = 0; k < 32; ++k) {
                ull a0 = dup2(zs[(rbase + 0) * ZSs + k]);
                ull a1 = dup2(zs[(rbase + 1) * ZSs + k]);
                ull a2 = dup2(zs[(rbase + 2) * ZSs + k]);
                ull a3 = dup2(zs[(rbase + 3) * ZSs + k]);
                #pragma unroll
                for (int j = 0; j < 4; ++j) {
                    ull w = *reinterpret_cast<const ull*>(wd + k * 130 + 2 * (pc + 16 * j));
                    acc[0][j] = fma2(a0, w, acc[0][j]);
                    acc[1][j] = fma2(a1, w, acc[1][j]);
                    acc[2][j] = fma2(a2, w, acc[2][j]);
                    acc[3][j] = fma2(a3, w, acc[3][j]);
                }
            }
            #pragma unroll
            for (int j = 0; j < 4; ++j) {
                int p = pc + 16 * j;
                if (p < npch) {
                    int c0 = (pbase + p) * 2;
                    float bb0 = b_d1[c0], bb1 = b_d1[c0 + 1];
                    #pragma unroll
                    for (int r = 0; r < 4; ++r) {
                        float2 a = unp(acc[r][j]);
                        float2 v;
                        v.x = fmaxf(a.x + bb0, 0.f);
                        v.y = fmaxf(a.y + bb1, 0.f);
                        *reinterpret_cast<float2*>(hs + (rbase + r) * HSs + c0) = v;
                    }
                }
            }
        }
    }

    // ======== Phase D: mu_y / logvar_y GEMMs + sigmoid/nll epilogue ========
    {
        float* wm = stg;             // [14][130]
        float* wl = stg + 14 * 130;  // [14][130]
        for (int dc = 0; dc < 7; ++dc) {               // D = 784 = 6*128 + 16
            const int cb = dc * 128;
            ull macc[4][4], lacc[4][4];
            #pragma unroll
            for (int r = 0; r < 4; ++r)
                #pragma unroll
                for (int j = 0; j < 4; ++j) { macc[r][j] = 0ull; lacc[r][j] = 0ull; }

            for (int kc = 0; kc < 28; ++kc) {          // K = 392 = 28*14
                const int kb = kc * 14;
                __syncthreads();
                #pragma unroll
                for (int i = 0; i < 7; ++i) {          // 1792 elems per matrix
                    int idx = tid + NT * i;
                    int c = idx / 14, kk = idx % 14;
                    int gc = cb + c;
                    bool ok = (gc < Dn);
                    size_t off = (size_t)gc * Hn + kb + kk;
                    wm[kk * 130 + c] = ok ? W_dmu[off] : 0.f;
                    wl[kk * 130 + c] = ok ? W_dlv[off] : 0.f;
                }
                __syncthreads();
                #pragma unroll
                for (int kk = 0; kk < 14; ++kk) {
                    ull a0 = dup2(hs[(rbase + 0) * HSs + kb + kk]);
                    ull a1 = dup2(hs[(rbase + 1) * HSs + kb + kk]);
                    ull a2 = dup2(hs[(rbase + 2) * HSs + kb + kk]);
                    ull a3 = dup2(hs[(rbase + 3) * HSs + kb + kk]);
                    #pragma unroll
                    for (int j = 0; j < 4; ++j) {
                        ull wmv = *reinterpret_cast<const ull*>(wm + kk * 130 + 2 * (pc + 16 * j));
                        ull wlv = *reinterpret_cast<const ull*>(wl + kk * 130 + 2 * (pc + 16 * j));
                        macc[0][j] = fma2(a0, wmv, macc[0][j]);
                        macc[1][j] = fma2(a1, wmv, macc[1][j]);
                        macc[2][j] = fma2(a2, wmv, macc[2][j]);
                        macc[3][j] = fma2(a3, wmv, macc[3][j]);
                        lacc[0][j] = fma2(a0, wlv, lacc[0][j]);
                        lacc[1][j] = fma2(a1, wlv, lacc[1][j]);
                        lacc[2][j] = fma2(a2, wlv, lacc[2][j]);
                        lacc[3][j] = fma2(a3, wlv, lacc[3][j]);
                    }
                }
            }
            #pragma unroll
            for (int j = 0; j < 4; ++j) {
                int p  = pc + 16 * j;
                int c0 = cb + 2 * p;
                if (c0 < Dn) {
                    float bm0 = b_dmu[c0], bm1 = b_dmu[c0 + 1];
                    float bl0 = b_dlv[c0], bl1 = b_dlv[c0 + 1];
                    #pragma unroll
                    for (int r = 0; r < 4; ++r) {
                        int grow = row0 + rbase + r;
                        float2 mm = unp(macc[r][j]);
                        float2 ll = unp(lacc[r][j]);
                        float mu0 = fmaxf(mm.x + bm0, 0.f), mu1 = fmaxf(mm.y + bm1, 0.f);
                        float lv0 = fmaxf(ll.x + bl0, 0.f), lv1 = fmaxf(ll.y + bl1, 0.f);
                        float ex0 = expf(0.5f * lv0), ex1 = expf(0.5f * lv1);
                        float2 ey = *reinterpret_cast<const float2*>(eps_y + (size_t)grow * Dn + c0);
                        float2 xv = *reinterpret_cast<const float2*>(x     + (size_t)grow * Dn + c0);
                        float t0 = mu0 + ey.x * ex0;
                        float t1 = mu1 + ey.y * ex1;
                        float2 o;
                        o.x = __fdividef(1.f, 1.f + expf(-t0));
                        o.y = __fdividef(1.f, 1.f + expf(-t1));
                        *reinterpret_cast<float2*>(out + (size_t)grow * Dn + c0) = o;
                        float d0 = xv.x - mu0, d1 = xv.y - mu1;
                        nll_acc += 0.5f * lv0 + __fdividef(d0 * d0, ex0)
                                 + 0.5f * lv1 + __fdividef(d1 * d1, ex1);
                    }
                }
            }
        }
    }

    // ================= deterministic block reduction of partials =================
    __syncthreads();
    float* red = stg;  // 512 floats
    red[tid]      = nll_acc;
    red[NT + tid] = kl_acc;
    __syncthreads();
    #pragma unroll
    for (int s = NT / 2; s > 0; s >>= 1) {
        if (tid < s) {
            red[tid]      += red[tid + s];
            red[NT + tid] += red[NT + tid + s];
        }
        __syncthreads();
    }
    if (tid == 0) {
        g_part[blockIdx.x * 2 + 0] = red[0];
        g_part[blockIdx.x * 2 + 1] = red[NT];
    }
}

// Deterministic final reduction -> scalar loss at out[out_size-1]
__global__ void vae_finalize(float* __restrict__ out, int out_size)
{
    __shared__ double rn[256], rk[256];
    int tid = threadIdx.x;
    double sn = 0.0, sk = 0.0;
    for (int i = tid; i < NCTA; i += 256) {
        sn += (double)g_part[2 * i + 0];
        sk += (double)g_part[2 * i + 1];
    }
    rn[tid] = sn; rk[tid] = sk;
    __syncthreads();
    for (int s = 128; s > 0; s >>= 1) {
        if (tid < s) { rn[tid] += rn[tid + s]; rk[tid] += rk[tid + s]; }
        __syncthreads();
    }
    if (tid == 0) {
        double nll = 0.5 * (double)Dn * log(2.0 * 3.14159265358979323846)
                   + rn[0] / (2.0 * (double)Bn);
        double kl  = 0.5 * rk[0];
        out[out_size - 1] = (float)(nll + kl);
    }
}

extern "C" void kernel_launch(void* const* d_in, const int* in_sizes, int n_in,
                              void* d_out, int out_size)
{
    const float* x     = (const float*)d_in[0];
    const float* eps_z = (const float*)d_in[1];
    const float* eps_y = (const float*)d_in[2];
    const float* W_e1  = (const float*)d_in[3];
    const float* b_e1  = (const float*)d_in[4];
    const float* W_emu = (const float*)d_in[5];
    const float* b_emu = (const float*)d_in[6];
    const float* W_elv = (const float*)d_in[7];
    const float* b_elv = (const float*)d_in[8];
    const float* W_d1  = (const float*)d_in[9];
    const float* b_d1  = (const float*)d_in[10];
    const float* W_dmu = (const float*)d_in[11];
    const float* b_dmu = (const float*)d_in[12];
    const float* W_dlv = (const float*)d_in[13];
    const float* b_dlv = (const float*)d_in[14];
    float* out = (float*)d_out;

    cudaFuncSetAttribute(vae_fused, cudaFuncAttributeMaxDynamicSharedMemorySize, SMEM_BYTES);

    vae_fused<<<NCTA, NT, SMEM_BYTES>>>(x, eps_z, eps_y,
                                        W_e1, b_e1, W_emu, b_emu, W_elv, b_elv,
                                        W_d1, b_d1, W_dmu, b_dmu, W_dlv, b_dlv,
                                        out);
    vae_finalize<<<1, 256>>>(out, out_size);
}

// round 6
// speedup vs baseline: 1.8628x; 1.8628x over previous
#include <cuda_runtime.h>
#include <cuda_bf16.h>
#include <math.h>
#include <stdint.h>

// ---------------- problem constants ----------------
#define BN 65536
#define DN 784
#define HN 392
#define LN 32

// ---------------- device scratch (static; no allocation) ----------------
__device__ float g_h [(size_t)BN * HN];
__device__ float g_z [(size_t)BN * LN];
__device__ float g_hd[(size_t)BN * HN];
__device__ float g_kl[512];
__device__ float g_nll[512 * 7];

// ---------------- helpers ----------------
__device__ __forceinline__ uint32_t sp_hi(float2 v, float2& lo) {
    __nv_bfloat162 h = __float22bfloat162_rn(v);
    lo.x = v.x - __bfloat162float(h.x);
    lo.y = v.y - __bfloat162float(h.y);
    return *reinterpret_cast<uint32_t*>(&h);
}
__device__ __forceinline__ uint32_t sp_pack(float2 v) {
    __nv_bfloat162 h = __float22bfloat162_rn(v);
    return *reinterpret_cast<uint32_t*>(&h);
}
__device__ __forceinline__ void hmma(float* c, const uint32_t* a, uint32_t b0, uint32_t b1) {
    asm volatile("mma.sync.aligned.m16n8k16.row.col.f32.bf16.bf16.f32 "
                 "{%0,%1,%2,%3}, {%4,%5,%6,%7}, {%8,%9}, {%0,%1,%2,%3};"
                 : "+f"(c[0]), "+f"(c[1]), "+f"(c[2]), "+f"(c[3])
                 : "r"(a[0]), "r"(a[1]), "r"(a[2]), "r"(a[3]), "r"(b0), "r"(b1));
}

// ============================================================================
// Phase GEMM kernels.  CTA = 256 threads = 8 warps (4 m-slabs x 2 n-groups).
// CTA tile M=128.  Warp tile m32 x n(NT8W*8).  bf16 hi/lo 3-mma split.
// SMEM staging is "fragment-major" so frag loads are LDS.128 / LDS.64.
//
// PH0: h  = relu(x W_e1^T + b)      K=784  N=392  (Ntile 112, grid n 4)
// PH1: mu/lv_z -> z, KL partials    K=392  N=64   (Ntile 64,  grid n 1)
// PH2: hd = relu(z W_d1^T + b)      K=32   N=392  (Ntile 112, grid n 4)
// PH3: mu/lv_y -> out, NLL partials K=392  N=224  (112 mu + 112 lv, grid n 7)
// ============================================================================
template <int PH>
__global__ __launch_bounds__(256)
void vae_mm(const float* __restrict__ x,    const float* __restrict__ eps_z,
            const float* __restrict__ eps_y,
            const float* __restrict__ We1,  const float* __restrict__ be1,
            const float* __restrict__ Wemu, const float* __restrict__ bemu,
            const float* __restrict__ Welv, const float* __restrict__ belv,
            const float* __restrict__ Wd1,  const float* __restrict__ bd1,
            const float* __restrict__ Wdmu, const float* __restrict__ bdmu,
            const float* __restrict__ Wdlv, const float* __restrict__ bdlv,
            float* __restrict__ out)
{
    constexpr int KD    = (PH == 0) ? 784 : (PH == 2) ? 32 : 392;
    constexpr int NK16  = (KD + 15) / 16;                   // 49, 25, 2, 25
    constexpr int NTILE = (PH == 1) ? 64 : (PH == 3) ? 224 : 112;
    constexpr int NT8   = NTILE / 8;                        // 14, 8, 14, 28
    constexpr int NT8W  = NT8 / 2;                          // 7, 4, 7, 14
    constexpr int NB    = NT8 * 64;                         // B u32 per term per k16
    constexpr int NBI   = (NB + 255) / 256;                 // 4, 2, 4, 7
    constexpr int BUFU  = 2048 + 2 * NB;                    // u32 per k16 buffer

    extern __shared__ __align__(16) uint32_t smu[];
    float* smf = reinterpret_cast<float*>(smu);

    const int tid  = threadIdx.x;
    const int lane = tid & 31, wid = tid >> 5;
    const int wm = wid >> 1, wn = wid & 1;
    const int m0 = blockIdx.x * 128;
    const int n0 = blockIdx.y * NTILE;      // weight-row base (PH0/PH2)
    const int cb = blockIdx.y * 112;        // mu/lv column base (PH3)

    const float* Ap = (PH == 0) ? x : (PH == 1) ? g_h : (PH == 2) ? g_z : g_hd;

    float acc[2][NT8W][4];
    #pragma unroll
    for (int t = 0; t < 2; ++t)
        #pragma unroll
        for (int n = 0; n < NT8W; ++n)
            #pragma unroll
            for (int q = 0; q < 4; ++q) acc[t][n][q] = 0.f;

    float2 ra[4];
    float2 rb[NBI];

    auto loadstep = [&](int s) {
        const int kb = s * 16;
        #pragma unroll
        for (int i = 0; i < 4; ++i) {
            int idx = tid + 256 * i;                 // 0..1023
            int m = idx >> 3, kp = idx & 7, k = kb + kp * 2;
            ra[i] = (k < KD) ? *reinterpret_cast<const float2*>(Ap + (size_t)(m0 + m) * KD + k)
                             : make_float2(0.f, 0.f);
        }
        #pragma unroll
        for (int i = 0; i < NBI; ++i) {
            int idx = tid + 256 * i;
            float2 v = make_float2(0.f, 0.f);
            if (idx < NB) {
                int n = idx >> 3, kp = idx & 7, k = kb + kp * 2;
                if (k < KD) {
                    if constexpr (PH == 0) {
                        int gn = n0 + n;
                        if (gn < HN) v = *reinterpret_cast<const float2*>(We1 + (size_t)gn * DN + k);
                    } else if constexpr (PH == 1) {
                        v = (n < 32) ? *reinterpret_cast<const float2*>(Wemu + (size_t)n * HN + k)
                                     : *reinterpret_cast<const float2*>(Welv + (size_t)(n - 32) * HN + k);
                    } else if constexpr (PH == 2) {
                        int gn = n0 + n;
                        if (gn < HN) v = *reinterpret_cast<const float2*>(Wd1 + (size_t)gn * LN + k);
                    } else {
                        if (n < 112) v = *reinterpret_cast<const float2*>(Wdmu + (size_t)(cb + n) * HN + k);
                        else         v = *reinterpret_cast<const float2*>(Wdlv + (size_t)(cb + n - 112) * HN + k);
                    }
                }
            }
            rb[i] = v;
        }
    };

    auto storestep = [&](uint32_t* buf) {
        #pragma unroll
        for (int i = 0; i < 4; ++i) {
            int idx = tid + 256 * i;
            int m = idx >> 3, kp = idx & 7;
            int t = m >> 4, rr = m & 15;
            int lpos = (rr & 7) * 4 + (kp & 3);
            int reg  = (rr >> 3) + 2 * (kp >> 2);
            float2 lo;
            uint32_t hi = sp_hi(ra[i], lo);
            int off = (t * 32 + lpos) * 4 + reg;
            buf[off]        = hi;
            buf[1024 + off] = sp_pack(lo);
        }
        #pragma unroll
        for (int i = 0; i < NBI; ++i) {
            int idx = tid + 256 * i;
            if (idx < NB) {
                int n = idx >> 3, kp = idx & 7;
                int nt = n >> 3, col = n & 7;
                int lpos = col * 4 + (kp & 3);
                int reg  = kp >> 2;
                float2 lo;
                uint32_t hi = sp_hi(rb[i], lo);
                int off = (nt * 32 + lpos) * 2 + reg;
                buf[2048 + off]      = hi;
                buf[2048 + NB + off] = sp_pack(lo);
            }
        }
    };

    // ---- mainloop: double-buffered k16 chunks with register prefetch ----
    loadstep(0);
    storestep(smu);
    __syncthreads();
    for (int s = 0; s < NK16; ++s) {
        uint32_t* cur = smu + (s & 1) * BUFU;
        uint32_t* nxt = smu + ((s + 1) & 1) * BUFU;
        if (s + 1 < NK16) loadstep(s + 1);

        uint32_t ah[2][4], al[2][4];
        #pragma unroll
        for (int t2 = 0; t2 < 2; ++t2) {
            const uint32_t* p = cur + ((wm * 2 + t2) * 32 + lane) * 4;
            uint4 vh = *reinterpret_cast<const uint4*>(p);
            uint4 vl = *reinterpret_cast<const uint4*>(p + 1024);
            ah[t2][0] = vh.x; ah[t2][1] = vh.y; ah[t2][2] = vh.z; ah[t2][3] = vh.w;
            al[t2][0] = vl.x; al[t2][1] = vl.y; al[t2][2] = vl.z; al[t2][3] = vl.w;
        }
        #pragma unroll
        for (int nn = 0; nn < NT8W; ++nn) {
            const uint32_t* pb = cur + 2048 + ((wn * NT8W + nn) * 32 + lane) * 2;
            uint2 vbh = *reinterpret_cast<const uint2*>(pb);
            uint2 vbl = *reinterpret_cast<const uint2*>(pb + NB);
            #pragma unroll
            for (int t2 = 0; t2 < 2; ++t2) {
                hmma(acc[t2][nn], ah[t2], vbh.x, vbh.y);
                hmma(acc[t2][nn], ah[t2], vbl.x, vbl.y);
                hmma(acc[t2][nn], al[t2], vbh.x, vbh.y);
            }
        }
        if (s + 1 < NK16) storestep(nxt);
        __syncthreads();
    }

    // ---------------- epilogues ----------------
    if constexpr (PH == 0 || PH == 2) {
        const float* bias = (PH == 0) ? be1 : bd1;
        float* dst = (PH == 0) ? g_h : g_hd;
        #pragma unroll
        for (int t2 = 0; t2 < 2; ++t2) {
            int r0 = m0 + wm * 32 + t2 * 16 + (lane >> 2);
            #pragma unroll
            for (int nn = 0; nn < NT8W; ++nn) {
                int col = n0 + wn * (NT8W * 8) + nn * 8 + (lane & 3) * 2;
                if (col < HN) {
                    float b0 = __ldg(bias + col), b1 = __ldg(bias + col + 1);
                    float2 v0, v1;
                    v0.x = fmaxf(acc[t2][nn][0] + b0, 0.f);
                    v0.y = fmaxf(acc[t2][nn][1] + b1, 0.f);
                    v1.x = fmaxf(acc[t2][nn][2] + b0, 0.f);
                    v1.y = fmaxf(acc[t2][nn][3] + b1, 0.f);
                    *reinterpret_cast<float2*>(dst + (size_t)r0 * HN + col) = v0;
                    *reinterpret_cast<float2*>(dst + (size_t)(r0 + 8) * HN + col) = v1;
                }
            }
        }
    }

    float part = 0.f;

    if constexpr (PH == 1) {
        // bounce C[128][64] through smem (stride 66), then elementwise reparam + KL
        float* csm = smf;
        #pragma unroll
        for (int t2 = 0; t2 < 2; ++t2) {
            int r = wm * 32 + t2 * 16 + (lane >> 2);
            #pragma unroll
            for (int nn = 0; nn < NT8W; ++nn) {
                int col = wn * 32 + nn * 8 + (lane & 3) * 2;
                *reinterpret_cast<float2*>(csm + r * 66 + col) =
                    make_float2(acc[t2][nn][0], acc[t2][nn][1]);
                *reinterpret_cast<float2*>(csm + (r + 8) * 66 + col) =
                    make_float2(acc[t2][nn][2], acc[t2][nn][3]);
            }
        }
        __syncthreads();
        #pragma unroll
        for (int i = 0; i < 16; ++i) {
            int e = tid + 256 * i;           // 128*32 = 4096 elems
            int row = e >> 5, l = e & 31;
            float mu = fmaxf(csm[row * 66 + l]      + __ldg(bemu + l), 0.f);
            float lv = fmaxf(csm[row * 66 + l + 32] + __ldg(belv + l), 0.f);
            float ev = expf(lv);
            int grow = m0 + row;
            float z = mu + eps_z[(size_t)grow * LN + l] * expf(0.5f * lv);
            g_z[(size_t)grow * LN + l] = z;
            part += mu * mu + ev - logf(1e-8f + ev) - 1.f;
        }
        __syncthreads();
    }

    if constexpr (PH == 3) {
        constexpr int CS3 = 226;
        float* csm = smf;
        for (int rd = 0; rd < 2; ++rd) {     // rows 0..63, then 64..127
            __syncthreads();
            if ((wm >> 1) == rd) {
                #pragma unroll
                for (int t2 = 0; t2 < 2; ++t2) {
                    int lr = (wm & 1) * 32 + t2 * 16 + (lane >> 2);
                    #pragma unroll
                    for (int nn = 0; nn < NT8W; ++nn) {
                        int col = wn * 112 + nn * 8 + (lane & 3) * 2;
                        *reinterpret_cast<float2*>(csm + lr * CS3 + col) =
                            make_float2(acc[t2][nn][0], acc[t2][nn][1]);
                        *reinterpret_cast<float2*>(csm + (lr + 8) * CS3 + col) =
                            make_float2(acc[t2][nn][2], acc[t2][nn][3]);
                    }
                }
            }
            __syncthreads();
            #pragma unroll
            for (int i = 0; i < 28; ++i) {
                int e = tid + 256 * i;       // 64*112 = 7168 pairs
                int row = e / 112, j = e - row * 112;
                int jj = cb + j;
                float mu = fmaxf(csm[row * CS3 + j]       + __ldg(bdmu + jj), 0.f);
                float lv = fmaxf(csm[row * CS3 + j + 112] + __ldg(bdlv + jj), 0.f);
                float ex = expf(0.5f * lv);
                int grow = m0 + rd * 64 + row;
                size_t o = (size_t)grow * DN + jj;
                float t = mu + eps_y[o] * ex;
                out[o] = 1.f / (1.f + expf(-t));
                float d = x[o] - mu;
                part += 0.5f * lv + d * d / ex;
            }
        }
        __syncthreads();
    }

    // deterministic per-CTA partial reduction (PH1: KL, PH3: NLL)
    if constexpr (PH == 1 || PH == 3) {
        float* red = smf;
        red[tid] = part;
        __syncthreads();
        #pragma unroll
        for (int s = 128; s > 0; s >>= 1) {
            if (tid < s) red[tid] += red[tid + s];
            __syncthreads();
        }
        if (tid == 0) {
            if constexpr (PH == 1) g_kl[blockIdx.x] = red[0];
            else                   g_nll[blockIdx.y * 512 + blockIdx.x] = red[0];
        }
    }
}

// ---------------- finalize: deterministic scalar loss ----------------
__global__ void vae_finalize(float* __restrict__ out, int out_size)
{
    __shared__ double rn[256], rk[256];
    int tid = threadIdx.x;
    double sn = 0.0, sk = 0.0;
    for (int i = tid; i < 512 * 7; i += 256) sn += (double)g_nll[i];
    for (int i = tid; i < 512;     i += 256) sk += (double)g_kl[i];
    rn[tid] = sn; rk[tid] = sk;
    __syncthreads();
    for (int s = 128; s > 0; s >>= 1) {
        if (tid < s) { rn[tid] += rn[tid + s]; rk[tid] += rk[tid + s]; }
        __syncthreads();
    }
    if (tid == 0) {
        double nll = 0.5 * (double)DN * log(2.0 * 3.14159265358979323846)
                   + rn[0] / (2.0 * (double)BN);
        out[out_size - 1] = (float)(nll + 0.5 * rk[0]);
    }
}

// ---------------- launch ----------------
extern "C" void kernel_launch(void* const* d_in, const int* in_sizes, int n_in,
                              void* d_out, int out_size)
{
    const float* x     = (const float*)d_in[0];
    const float* eps_z = (const float*)d_in[1];
    const float* eps_y = (const float*)d_in[2];
    const float* W_e1  = (const float*)d_in[3];
    const float* b_e1  = (const float*)d_in[4];
    const float* W_emu = (const float*)d_in[5];
    const float* b_emu = (const float*)d_in[6];
    const float* W_elv = (const float*)d_in[7];
    const float* b_elv = (const float*)d_in[8];
    const float* W_d1  = (const float*)d_in[9];
    const float* b_d1  = (const float*)d_in[10];
    const float* W_dmu = (const float*)d_in[11];
    const float* b_dmu = (const float*)d_in[12];
    const float* W_dlv = (const float*)d_in[13];
    const float* b_dlv = (const float*)d_in[14];
    float* out = (float*)d_out;

    // dynamic smem: max(2 staging buffers, epilogue bounce)
    const int SB0 = 2 * (2048 + 2 * 14 * 64) * 4;               // 30720
    const int SB1 = 128 * 66 * 4;                               // 33792 (> 24576 staging)
    const int SB2 = SB0;                                        // 30720
    const int SB3 = 64 * 226 * 4;                               // 57856 (> 45056 staging)
    cudaFuncSetAttribute(vae_mm<0>, cudaFuncAttributeMaxDynamicSharedMemorySize, SB0);
    cudaFuncSetAttribute(vae_mm<1>, cudaFuncAttributeMaxDynamicSharedMemorySize, SB1);
    cudaFuncSetAttribute(vae_mm<2>, cudaFuncAttributeMaxDynamicSharedMemorySize, SB2);
    cudaFuncSetAttribute(vae_mm<3>, cudaFuncAttributeMaxDynamicSharedMemorySize, SB3);

    dim3 g0(512, 4), g1(512, 1), g2(512, 4), g3(512, 7);
    vae_mm<0><<<g0, 256, SB0>>>(x, eps_z, eps_y, W_e1, b_e1, W_emu, b_emu,
                                W_elv, b_elv, W_d1, b_d1, W_dmu, b_dmu, W_dlv, b_dlv, out);
    vae_mm<1><<<g1, 256, SB1>>>(x, eps_z, eps_y, W_e1, b_e1, W_emu, b_emu,
                                W_elv, b_elv, W_d1, b_d1, W_dmu, b_dmu, W_dlv, b_dlv, out);
    vae_mm<2><<<g2, 256, SB2>>>(x, eps_z, eps_y, W_e1, b_e1, W_emu, b_emu,
                                W_elv, b_elv, W_d1, b_d1, W_dmu, b_dmu, W_dlv, b_dlv, out);
    vae_mm<3><<<g3, 256, SB3>>>(x, eps_z, eps_y, W_e1, b_e1, W_emu, b_emu,
                                W_elv, b_elv, W_d1, b_d1, W_dmu, b_dmu, W_dlv, b_dlv, out);
    vae_finalize<<<1, 256>>>(out, out_size);
}